// round 15
// baseline (speedup 1.0000x reference)
#include <cuda_runtime.h>
#include <cuda_fp16.h>
#include <math.h>

#define BATCH 8
#define HP 256        // pooled H/W
#define HF 512        // full H/W
#define BX 32
#define BY 32
#define PR 39         // pooled rows loaded  (tileY-4 .. tileY+34)
#define PC 39         // pooled cols loaded  (tileX-4 .. tileX+34)
#define PCW 40        // pooled col stride
#define DR 34         // diff rows (tileY-1 .. tileY+32)
#define DC 34         // diff cols (tileX-1 .. tileX+32)
#define HROWS 38      // BY+6
#define VROWS 36      // BY+4

// Scratch (device globals — zero-initialized; self-resetting each run)
__device__ unsigned int g_hist_agg[BATCH][256];
__device__ float g_part_mind[512];
__device__ float g_part_reg[256];
__device__ unsigned int g_done;

__device__ __forceinline__ int clampi(int v, int lo, int hi) { return min(max(v, lo), hi); }

// ---- packed f32x2 ops (sm_103a) ----
__device__ __forceinline__ float2 f2add(float2 a, float2 b) {
    float2 r;
    asm("add.rn.f32x2 %0, %1, %2;"
        : "=l"(reinterpret_cast<unsigned long long&>(r))
        : "l"(reinterpret_cast<unsigned long long&>(a)),
          "l"(reinterpret_cast<unsigned long long&>(b)));
    return r;
}
__device__ __forceinline__ float2 f2mul(float2 a, float2 b) {
    float2 r;
    asm("mul.rn.f32x2 %0, %1, %2;"
        : "=l"(reinterpret_cast<unsigned long long&>(r))
        : "l"(reinterpret_cast<unsigned long long&>(a)),
          "l"(reinterpret_cast<unsigned long long&>(b)));
    return r;
}
__device__ __forceinline__ float2 f2fma(float2 a, float2 b, float2 c) {
    float2 r;
    asm("fma.rn.f32x2 %0, %1, %2, %3;"
        : "=l"(reinterpret_cast<unsigned long long&>(r))
        : "l"(reinterpret_cast<unsigned long long&>(a)),
          "l"(reinterpret_cast<unsigned long long&>(b)),
          "l"(reinterpret_cast<unsigned long long&>(c)));
    return r;
}
__device__ __forceinline__ float ex2f(float x) {
    float r;
    asm("ex2.approx.ftz.f32 %0, %1;" : "=f"(r) : "f"(x));
    return r;
}
#define LOG2E 1.4426950408889634f

// ============ single fused kernel ============
// blocks [0,512): MIND tiles 32x32: pool+hist+descriptors+diff+upsample+partials
// blocks [512,768): flow regularizer strips
__global__ __launch_bounds__(512, 3) void k_main(const float* __restrict__ fixed,
                                                 const float* __restrict__ moved,
                                                 const float* __restrict__ flow,
                                                 float* __restrict__ out) {
    __shared__ __align__(16) union {
        struct {
            float2 sFM[PR][PCW];                 // pooled (F,M) + 4-halo   12480B
            float2 bufA[HROWS * 36];             // h -> hv / inv           10944B
            char   bufB[DR * 36 * 16];           // v (float2) -> dp (uint4)19584B
            float2 ytab[64];
            unsigned int sh[256];
            float red[16];
        } m;
        struct { float su[10][256], sv[10][256]; float red[512]; } r;
        struct { float hp[8][256]; float xh[8][16], yh[8][16];
                 float nmi[8]; float mind_p[4]; float reg_p[2]; } e;
    } S;

    const float SCALE = 255.0f / 511.0f;
    const float2 NNINTH = make_float2(-1.0f / 9.0f, -1.0f / 9.0f);
    int blk = blockIdx.x;
    int tid = threadIdx.x;

    if (blk < 512) {
        // ================= MIND tile (32x32 pooled px) =================
        int b = blk >> 6;
        int rem = blk & 63;
        int bxi = rem & 7, byi = rem >> 3;
        int tileX = bxi * BX, tileY = byi * BY;
        int gx0 = tileX - 4, gy0 = tileY - 4;
        const float* fF = fixed + (size_t)b * HF * HF;
        const float* fM = moved + (size_t)b * HF * HF;
        bool interior = (bxi >= 1) && (bxi <= 6) && (byi >= 1) && (byi <= 6);

        float2* A = S.m.bufA;
        float2* vB = (float2*)S.m.bufB;          // v stage (36x36, stride 36)
        uint4*  dpB = (uint4*)S.m.bufB;          // diff stage (34x36, stride 36)

        if (tid < 256) S.m.sh[tid] = 0u;

        // hist raw samples: 2 pooled pixels per thread (rows ty, ty+16)
        int ty = tid >> 5, tx = tid & 31;
        float a0 = __ldg(&fF[(size_t)(2 * (tileY + ty)) * HF + 2 * (tileX + tx)]);
        float m0 = __ldg(&fM[(size_t)(2 * (tileY + ty)) * HF + 2 * (tileX + tx)]);
        float a1 = __ldg(&fF[(size_t)(2 * (tileY + ty + 16)) * HF + 2 * (tileX + tx)]);
        float m1 = __ldg(&fM[(size_t)(2 * (tileY + ty + 16)) * HF + 2 * (tileX + tx)]);

        // y upsample table for this tile's 64 output rows
        if (tid < 64) {
            float pos = (float)(2 * tileY + tid) * SCALE;
            int i0 = clampi((int)floorf(pos), 0, HP - 2);
            S.m.ytab[tid] = make_float2(pos - (float)i0, __int_as_float(i0 - (tileY - 1)));
        }

        // pooled loader (from full-res), 4-halo, packed (F,M)
        if (interior) {
            for (int s = tid; s < PR * PC; s += 512) {
                int sy = s / PC, sx = s % PC;
                int gy = gy0 + sy, gx = gx0 + sx;
                const float2* pF = (const float2*)(fF + (size_t)(2 * gy) * HF) + gx;
                float2 tF = f2add(pF[0], pF[HF / 2]);
                const float2* pM = (const float2*)(fM + (size_t)(2 * gy) * HF) + gx;
                float2 tM = f2add(pM[0], pM[HF / 2]);
                S.m.sFM[sy][sx] = make_float2(0.25f * (tF.x + tF.y), 0.25f * (tM.x + tM.y));
            }
        } else {
            for (int s = tid; s < PR * PC; s += 512) {
                int sy = s / PC, sx = s % PC;
                int gy = clampi(gy0 + sy, 0, HP - 1), gx = clampi(gx0 + sx, 0, HP - 1);
                const float2* pF = (const float2*)(fF + (size_t)(2 * gy) * HF) + gx;
                float2 tF = f2add(pF[0], pF[HF / 2]);
                const float2* pM = (const float2*)(fM + (size_t)(2 * gy) * HF) + gx;
                float2 tM = f2add(pM[0], pM[HF / 2]);
                S.m.sFM[sy][sx] = make_float2(0.25f * (tF.x + tF.y), 0.25f * (tM.x + tM.y));
            }
        }
        __syncthreads();

        // histogram (shared atomics; searchsorted-left == ceil(v*16)-1 on exact grid)
        {
            float xf = fminf(fmaxf((a0 + 1.0f) * 0.5f, 0.001f), 0.999f);
            float yf = fminf(fmaxf((m0 + 1.0f) * 0.5f, 0.001f), 0.999f);
            int xb = clampi((int)ceilf(xf * 16.0f) - 1, 0, 15);
            int yb = clampi((int)ceilf(yf * 16.0f) - 1, 0, 15);
            atomicAdd(&S.m.sh[xb * 16 + yb], 1u);
            xf = fminf(fmaxf((a1 + 1.0f) * 0.5f, 0.001f), 0.999f);
            yf = fminf(fmaxf((m1 + 1.0f) * 0.5f, 0.001f), 0.999f);
            xb = clampi((int)ceilf(xf * 16.0f) - 1, 0, 15);
            yb = clampi((int)ceilf(yf * 16.0f) - 1, 0, 15);
            atomicAdd(&S.m.sh[xb * 16 + yb], 1u);
        }

        if (interior) {
            // h -> A
            for (int s = tid; s < HROWS * 36; s += 512) {
                int u = s / 36, j = s % 36;
                A[s] = f2add(f2add(S.m.sFM[u][j], S.m.sFM[u][j + 1]), S.m.sFM[u][j + 2]);
            }
            __syncthreads();
            // variance_pre -> vB
            for (int s = tid; s < VROWS * 36; s += 512) {
                int iy = s / 36, jx = s % 36;
                float2 pm = f2add(f2add(A[s], A[s + 36]), A[s + 72]);
                float2 d = f2fma(pm, NNINTH, S.m.sFM[iy + 2][jx + 2]);
                vB[s] = f2mul(d, d);
            }
            __syncthreads();
            // hv -> A (h dead)
            for (int s = tid; s < VROWS * 34; s += 512) {
                int iy = s / 34, mc = s % 34;
                A[iy * 36 + mc] = f2add(f2add(vB[iy * 36 + mc], vB[iy * 36 + mc + 1]),
                                        vB[iy * 36 + mc + 2]);
            }
            __syncthreads();
        } else {
            // border: variance_pre (clamped taps) -> vB
            for (int s = tid; s < VROWS * 36; s += 512) {
                int iy = s / 36, jx = s % 36;
                int gv = tileY - 2 + iy, gc = tileX - 2 + jx;
                float2 pm = make_float2(0.f, 0.f);
                #pragma unroll
                for (int aa = 0; aa < 3; aa++) {
                    int rr = clampi(gv - 2 + aa, 0, HP - 1) - gy0;
                    #pragma unroll
                    for (int bb = 0; bb < 3; bb++) {
                        int cc = clampi(gc - 2 + bb, 0, HP - 1) - gx0;
                        pm = f2add(pm, S.m.sFM[rr][cc]);
                    }
                }
                float2 d = f2fma(pm, NNINTH, S.m.sFM[iy + 2][jx + 2]);
                vB[s] = f2mul(d, d);
            }
            __syncthreads();
            // border: inv pre-stage -> A (so dp can overwrite vB)
            for (int s = tid; s < DR * DC; s += 512) {
                int a = s / DC, b2 = s % DC;
                int gdy = tileY - 1 + a, gdx = tileX - 1 + b2;
                float2 vs = make_float2(0.f, 0.f);
                #pragma unroll
                for (int dy2 = -1; dy2 <= 1; dy2++) {
                    int iy = clampi(gdy + dy2, 0, HP - 1) - (tileY - 2);
                    #pragma unroll
                    for (int dx2 = -1; dx2 <= 1; dx2++) {
                        int jx = clampi(gdx + dx2, 0, HP - 1) - (tileX - 2);
                        vs = f2add(vs, vB[iy * 36 + jx]);
                    }
                }
                float varF = fmaxf(vs.x * (1.0f / 9.0f), 1e-4f);
                float varM = fmaxf(vs.y * (1.0f / 9.0f), 1e-4f);
                A[a * 36 + b2] = make_float2(LOG2E / (varF * 2.0f + 1e-6f),
                                             LOG2E / (varM * 2.0f + 1e-6f));
            }
            __syncthreads();
        }

        // diff channels on DRxDC; exponent via ex2 (log2e folded into inv)
        {
            const int offdx[8] = {-2, -2, -2, 0, 0, 2, 2, 2};
            const int offdy[8] = {-2, 0, 2, -2, 2, -2, 0, 2};
            for (int s = tid; s < DR * DC; s += 512) {
                int a = s / DC, b2 = s % DC;
                float2 iFM;
                if (interior) {
                    float2 vs = f2add(f2add(A[a * 36 + b2], A[(a + 1) * 36 + b2]),
                                      A[(a + 2) * 36 + b2]);
                    float varF = fmaxf(vs.x * (1.0f / 9.0f), 1e-4f);
                    float varM = fmaxf(vs.y * (1.0f / 9.0f), 1e-4f);
                    iFM = make_float2(LOG2E / (varF * 2.0f + 1e-6f),
                                      LOG2E / (varM * 2.0f + 1e-6f));
                } else {
                    iFM = A[a * 36 + b2];
                }
                float2 c0 = S.m.sFM[a + 3][b2 + 3];

                float eF[8], eM[8];
                float sumF = 0.f, sumM = 0.f;
                if (interior) {
                    #pragma unroll
                    for (int c = 0; c < 8; c++) {
                        float2 o = S.m.sFM[a + 3 + offdy[c]][b2 + 3 + offdx[c]];
                        float2 df = make_float2(c0.x - o.x, c0.y - o.y);
                        float2 q = f2mul(f2mul(df, df), iFM);
                        eF[c] = ex2f(-q.x); eM[c] = ex2f(-q.y);
                        sumF += eF[c]; sumM += eM[c];
                    }
                } else {
                    #pragma unroll
                    for (int c = 0; c < 8; c++) {
                        int rr = clampi(tileY - 1 + a + offdy[c], 0, HP - 1) - gy0;
                        int cc = clampi(tileX - 1 + b2 + offdx[c], 0, HP - 1) - gx0;
                        float2 o = S.m.sFM[rr][cc];
                        float2 df = make_float2(c0.x - o.x, c0.y - o.y);
                        float2 q = f2mul(f2mul(df, df), iFM);
                        eF[c] = ex2f(-q.x); eM[c] = ex2f(-q.y);
                        sumF += eF[c]; sumM += eM[c];
                    }
                }
                float rF = 1.0f / (sumF + 1e-8f), rM = 1.0f / (sumM + 1e-8f);
                __half2 tmp4[4];
                #pragma unroll
                for (int p = 0; p < 4; p++) {
                    float d0 = eF[2 * p] * rF - eM[2 * p] * rM;
                    float d1 = eF[2 * p + 1] * rF - eM[2 * p + 1] * rM;
                    tmp4[p] = __floats2half2_rn(d0, d1);
                }
                dpB[a * 36 + b2] = *(uint4*)tmp4;
            }
        }
        __syncthreads();

        // ---- in-tile bilinear upsample (align corners) + |.| accumulate ----
        // 64x64 outputs; thread owns col lx, two 4-row groups (qy, qy+8)
        float acc = 0.f;
        {
            int lx = tid & 63;
            float posx = (float)(2 * tileX + lx) * SCALE;
            int j0 = clampi((int)floorf(posx), 0, HP - 2);
            float fx = posx - (float)j0;
            int rx = j0 - (tileX - 1);       // 0..32
            __half2 wx0 = __float2half2_rn(1.0f - fx), wx1 = __float2half2_rn(fx);

            #pragma unroll
            for (int half = 0; half < 2; half++) {
                int qy = (tid >> 6) + half * 8;    // 0..15
                float2 yt[4];
                #pragma unroll
                for (int k = 0; k < 4; k++) yt[k] = S.m.ytab[qy * 4 + k];
                int rbase = __float_as_int(yt[0].y);

                __half2 xv[4][4];
                #pragma unroll
                for (int rr = 0; rr < 4; rr++) {
                    int row = min(rbase + rr, DR - 1);
                    uint4 t0 = dpB[row * 36 + rx];
                    uint4 t1 = dpB[row * 36 + rx + 1];
                    const __half2* h0 = (const __half2*)&t0;
                    const __half2* h1 = (const __half2*)&t1;
                    #pragma unroll
                    for (int p = 0; p < 4; p++)
                        xv[p][rr] = __hfma2(h1[p], wx1, __hmul2(h0[p], wx0));
                }
                #pragma unroll
                for (int k = 0; k < 4; k++) {
                    float fy = yt[k].x;
                    int ri = __float_as_int(yt[k].y) - rbase;   // 0..2
                    __half2 wy0 = __float2half2_rn(1.0f - fy), wy1 = __float2half2_rn(fy);
                    #pragma unroll
                    for (int p = 0; p < 4; p++) {
                        __half2 val = __hfma2(xv[p][ri + 1], wy1, __hmul2(xv[p][ri], wy0));
                        float2 vf = __half22float2(val);
                        acc += fabsf(vf.x) + fabsf(vf.y);
                    }
                }
            }
        }
        // block reduce (deterministic)
        #pragma unroll
        for (int o = 16; o > 0; o >>= 1)
            acc += __shfl_down_sync(0xffffffffu, acc, o);
        if ((tid & 31) == 0) S.m.red[tid >> 5] = acc;
        __syncthreads();
        if (tid == 0) {
            float s = 0.f;
            #pragma unroll
            for (int k = 0; k < 16; k++) s += S.m.red[k];
            g_part_mind[blk] = s;
        }
        // flush per-tile histogram
        if (tid < 256) {
            unsigned int cnt = S.m.sh[tid];
            if (cnt) atomicAdd(&g_hist_agg[b][tid], cnt);
        }
    } else {
        // ================= regularizer strip =================
        int q = blk - 512;           // 0..255
        int b = q >> 5;
        int st = q & 31;             // 8 pooled rows per strip
        int sel = tid >> 8;          // 0 -> u, 1 -> v
        int tt = tid & 255;
        const float* base = flow + ((size_t)b * 2 + sel) * HF * HF;
        float (*sbuf)[256] = sel ? S.r.sv : S.r.su;

        #pragma unroll
        for (int rr = 0; rr < 10; rr++) {
            int py = clampi(st * 8 - 1 + rr, 0, HP - 1);
            const float2* p2 = (const float2*)(base + (size_t)(2 * py) * HF) + tt;
            float2 t2 = f2add(p2[0], p2[HF / 2]);
            sbuf[rr][tt] = 0.25f * (t2.x + t2.y);
        }
        __syncthreads();

        int x = tid & 255;
        int rg = tid >> 8;
        int xm = max(x - 1, 0), xp = min(x + 1, HP - 1);
        float acc = 0.f;
        #pragma unroll
        for (int k = 0; k < 4; k++) {
            int rr = rg * 4 + k + 1;
            float u00 = S.r.su[rr - 1][xm], u01 = S.r.su[rr - 1][x], u02 = S.r.su[rr - 1][xp];
            float u10 = S.r.su[rr][xm],     u11 = S.r.su[rr][x],     u12 = S.r.su[rr][xp];
            float u20 = S.r.su[rr + 1][xm], u21 = S.r.su[rr + 1][x], u22 = S.r.su[rr + 1][xp];
            float v00 = S.r.sv[rr - 1][xm], v01 = S.r.sv[rr - 1][x], v02 = S.r.sv[rr - 1][xp];
            float v10 = S.r.sv[rr][xm],     v11 = S.r.sv[rr][x],     v12 = S.r.sv[rr][xp];
            float v20 = S.r.sv[rr + 1][xm], v21 = S.r.sv[rr + 1][x], v22 = S.r.sv[rr + 1][xp];

            float gxu = (u02 + 2.f * u12 + u22) - (u00 + 2.f * u10 + u20);
            float gyu = (u20 + 2.f * u21 + u22) - (u00 + 2.f * u01 + u02);
            float lpu = u01 + u10 + u12 + u21 - 4.f * u11;
            float gxv = (v02 + 2.f * v12 + v22) - (v00 + 2.f * v10 + v20);
            float gyv = (v20 + 2.f * v21 + v22) - (v00 + 2.f * v01 + v02);
            float lpv = v01 + v10 + v12 + v21 - 4.f * v11;

            float gm = gxu * gxu + gyu * gyu + gxv * gxv + gyv * gyv;
            float lm = lpu * lpu + lpv * lpv;
            acc += fminf(gm, 100.0f) + fminf(lm, 100.0f);
        }
        __syncthreads();
        S.r.red[tid] = acc;
        __syncthreads();
        #pragma unroll
        for (int s = 256; s > 0; s >>= 1) {
            if (tid < s) S.r.red[tid] += S.r.red[tid + s];
            __syncthreads();
        }
        if (tid == 0) g_part_reg[q] = S.r.red[0];
    }

    // ================= last-block-done fused epilogue =================
    __threadfence();
    __syncthreads();
    __shared__ unsigned int isLast;
    if (tid == 0) isLast = (atomicAdd(&g_done, 1u) == (unsigned)(gridDim.x - 1)) ? 1u : 0u;
    __syncthreads();
    if (!isLast) return;

    int w = tid >> 5;
    int lane = tid & 31;

    if (w < 8) {
        int b = w;
        uint4 u0 = __ldcg((const uint4*)&g_hist_agg[b][0] + lane * 2);
        uint4 u1 = __ldcg((const uint4*)&g_hist_agg[b][0] + lane * 2 + 1);
        ((uint4*)&g_hist_agg[b][0])[lane * 2] = make_uint4(0, 0, 0, 0);
        ((uint4*)&g_hist_agg[b][0])[lane * 2 + 1] = make_uint4(0, 0, 0, 0);
        float p[8];
        p[0] = (float)u0.x * (1.0f / 65536.0f); p[1] = (float)u0.y * (1.0f / 65536.0f);
        p[2] = (float)u0.z * (1.0f / 65536.0f); p[3] = (float)u0.w * (1.0f / 65536.0f);
        p[4] = (float)u1.x * (1.0f / 65536.0f); p[5] = (float)u1.y * (1.0f / 65536.0f);
        p[6] = (float)u1.z * (1.0f / 65536.0f); p[7] = (float)u1.w * (1.0f / 65536.0f);
        #pragma unroll
        for (int k = 0; k < 8; k++) S.e.hp[b][lane * 8 + k] = p[k];
        __syncwarp();
        if (lane < 16) {
            float s = 0.f;
            #pragma unroll
            for (int j = 0; j < 16; j++) s += S.e.hp[b][lane * 16 + j];
            S.e.xh[b][lane] = s + 1e-5f;
        } else {
            int col = lane - 16;
            float s = 0.f;
            #pragma unroll
            for (int i = 0; i < 16; i++) s += S.e.hp[b][i * 16 + col];
            S.e.yh[b][col] = s + 1e-5f;
        }
        __syncwarp();
        int row = (lane * 8) >> 4;
        float xr = S.e.xh[b][row];
        int cbase = (lane * 8) & 15;
        float term = 0.f;
        #pragma unroll
        for (int k = 0; k < 8; k++) {
            float hpe = p[k] + 1e-5f;
            term += hpe * (__logf(hpe) - __logf(xr * S.e.yh[b][cbase + k]));
        }
        #pragma unroll
        for (int o = 16; o > 0; o >>= 1)
            term += __shfl_down_sync(0xffffffffu, term, o);
        if (lane == 0) {
            float mi = term;
            float hx = 0.f, hy = 0.f;
            #pragma unroll
            for (int k = 0; k < 16; k++) {
                hx -= S.e.xh[b][k] * __logf(S.e.xh[b][k]);
                hy -= S.e.yh[b][k] * __logf(S.e.yh[b][k]);
            }
            float se = hx + hy;
            float nmi = (se < 1e-10f) ? 0.0f : 2.0f * mi / se;
            S.e.nmi[b] = fminf(fmaxf(nmi, -1.0f), 1.0f);
        }
    } else if (w < 12) {
        // mind partials: 512 floats across warps 8-11 (float4/lane)
        int i = (w - 8) * 32 + lane;   // 0..127
        float4 v;
        v.x = __ldcg(&g_part_mind[4 * i]);
        v.y = __ldcg(&g_part_mind[4 * i + 1]);
        v.z = __ldcg(&g_part_mind[4 * i + 2]);
        v.w = __ldcg(&g_part_mind[4 * i + 3]);
        float s = (v.x + v.y) + (v.z + v.w);
        #pragma unroll
        for (int o = 16; o > 0; o >>= 1)
            s += __shfl_down_sync(0xffffffffu, s, o);
        if (lane == 0) S.e.mind_p[w - 8] = s;
    } else if (w < 14) {
        // reg partials: 256 floats across warps 12-13 (float4/lane)
        int j = (w - 12) * 32 + lane;   // 0..63
        float4 r4;
        r4.x = __ldcg(&g_part_reg[4 * j]);
        r4.y = __ldcg(&g_part_reg[4 * j + 1]);
        r4.z = __ldcg(&g_part_reg[4 * j + 2]);
        r4.w = __ldcg(&g_part_reg[4 * j + 3]);
        float sr = (r4.x + r4.y) + (r4.z + r4.w);
        #pragma unroll
        for (int o = 16; o > 0; o >>= 1)
            sr += __shfl_down_sync(0xffffffffu, sr, o);
        if (lane == 0) S.e.reg_p[w - 12] = sr;
    }
    __syncthreads();

    if (tid == 0) {
        float mind = S.e.mind_p[0] + S.e.mind_p[1] + S.e.mind_p[2] + S.e.mind_p[3];
        float reg = S.e.reg_p[0] + S.e.reg_p[1];
        float accn = 0.f;
        #pragma unroll
        for (int b = 0; b < BATCH; b++) accn += S.e.nmi[b];
        float mm = fminf(fmaxf(accn * (1.0f / BATCH), -1.0f), 1.0f);
        out[0] = -mm
               + 5.0f * (mind * (1.0f / 16777216.0f))
               + 0.1f * (reg * (1.0f / 524288.0f));
        g_done = 0u;   // reset for next graph replay
    }
}

// ---------------- launch ----------------
extern "C" void kernel_launch(void* const* d_in, const int* in_sizes, int n_in,
                              void* d_out, int out_size) {
    const float* fixed = (const float*)d_in[0];
    const float* moved = (const float*)d_in[1];
    const float* flow  = (const float*)d_in[2];
    if (n_in >= 3) {
        int fi = -1;
        for (int i = 0; i < 3; i++) if (in_sizes[i] == 2 * BATCH * HF * HF) fi = i;
        if (fi == 0) { flow = (const float*)d_in[0]; fixed = (const float*)d_in[1]; moved = (const float*)d_in[2]; }
        else if (fi == 1) { fixed = (const float*)d_in[0]; flow = (const float*)d_in[1]; moved = (const float*)d_in[2]; }
    }

    k_main<<<768, 512>>>(fixed, moved, flow, (float*)d_out);
}

// round 16
// speedup vs baseline: 1.0088x; 1.0088x over previous
#include <cuda_runtime.h>
#include <cuda_fp16.h>
#include <math.h>

#define BATCH 8
#define HP 256        // pooled H/W
#define HF 512        // full H/W
#define BX 32
#define BY 32
#define PR 39         // pooled rows loaded  (tileY-4 .. tileY+34)
#define PC 39         // pooled cols loaded  (tileX-4 .. tileX+34)
#define PCW 40        // pooled col stride
#define DR 34         // diff rows (tileY-1 .. tileY+32)
#define DC 34         // diff cols (tileX-1 .. tileX+32)
#define HROWS 38      // BY+6
#define VROWS 36      // BY+4

// Scratch (device globals — zero-initialized; self-resetting each run)
__device__ unsigned int g_hist_agg[BATCH][256];
__device__ float g_part_mind[512];
__device__ float g_part_reg[256];
__device__ unsigned int g_done;

__device__ __forceinline__ int clampi(int v, int lo, int hi) { return min(max(v, lo), hi); }

// ---- packed f32x2 ops (sm_103a) ----
__device__ __forceinline__ float2 f2add(float2 a, float2 b) {
    float2 r;
    asm("add.rn.f32x2 %0, %1, %2;"
        : "=l"(reinterpret_cast<unsigned long long&>(r))
        : "l"(reinterpret_cast<unsigned long long&>(a)),
          "l"(reinterpret_cast<unsigned long long&>(b)));
    return r;
}
__device__ __forceinline__ float2 f2mul(float2 a, float2 b) {
    float2 r;
    asm("mul.rn.f32x2 %0, %1, %2;"
        : "=l"(reinterpret_cast<unsigned long long&>(r))
        : "l"(reinterpret_cast<unsigned long long&>(a)),
          "l"(reinterpret_cast<unsigned long long&>(b)));
    return r;
}
__device__ __forceinline__ float2 f2fma(float2 a, float2 b, float2 c) {
    float2 r;
    asm("fma.rn.f32x2 %0, %1, %2, %3;"
        : "=l"(reinterpret_cast<unsigned long long&>(r))
        : "l"(reinterpret_cast<unsigned long long&>(a)),
          "l"(reinterpret_cast<unsigned long long&>(b)),
          "l"(reinterpret_cast<unsigned long long&>(c)));
    return r;
}
__device__ __forceinline__ float ex2f(float x) {
    float r;
    asm("ex2.approx.ftz.f32 %0, %1;" : "=f"(r) : "f"(x));
    return r;
}
#define LOG2E 1.4426950408889634f

__device__ __forceinline__ void hist_sample(unsigned int* sh, float fa, float mv) {
    float xf = fminf(fmaxf((fa + 1.0f) * 0.5f, 0.001f), 0.999f);
    float yf = fminf(fmaxf((mv + 1.0f) * 0.5f, 0.001f), 0.999f);
    // searchsorted(linspace(0,1,17),v,'left')-1 == ceil(v*16)-1 on exact grid
    int xb = clampi((int)ceilf(xf * 16.0f) - 1, 0, 15);
    int yb = clampi((int)ceilf(yf * 16.0f) - 1, 0, 15);
    atomicAdd(&sh[xb * 16 + yb], 1u);
}

// ============ single fused kernel ============
// blocks [0,512): MIND tiles 32x32: pool+hist+descriptors+diff+upsample+partials
// blocks [512,768): flow regularizer strips
__global__ __launch_bounds__(512, 3) void k_main(const float* __restrict__ fixed,
                                                 const float* __restrict__ moved,
                                                 const float* __restrict__ flow,
                                                 float* __restrict__ out) {
    __shared__ __align__(16) union {
        struct {
            float2 sFM[PR][PCW];                 // pooled (F,M) + 4-halo   12480B
            float2 bufA[HROWS * 36];             // h -> hv / -inv          10944B
            char   bufB[DR * 36 * 16];           // v (float2) -> dp (uint4)19584B
            float2 ytab[64];
            unsigned int sh[256];
            float red[16];
        } m;
        struct { float su[10][256], sv[10][256]; float red[512]; } r;
        struct { float hp[8][256]; float xh[8][16], yh[8][16];
                 float nmi[8]; float mind_p[4]; float reg_p[2]; } e;
    } S;

    const float SCALE = 255.0f / 511.0f;
    const float2 NNINTH = make_float2(-1.0f / 9.0f, -1.0f / 9.0f);
    int blk = blockIdx.x;
    int tid = threadIdx.x;

    if (blk < 512) {
        // ================= MIND tile (32x32 pooled px) =================
        int b = blk >> 6;
        int rem = blk & 63;
        int bxi = rem & 7, byi = rem >> 3;
        int tileX = bxi * BX, tileY = byi * BY;
        int gx0 = tileX - 4, gy0 = tileY - 4;
        const float* fF = fixed + (size_t)b * HF * HF;
        const float* fM = moved + (size_t)b * HF * HF;
        bool interior = (bxi >= 1) && (bxi <= 6) && (byi >= 1) && (byi <= 6);

        float2* A = S.m.bufA;
        float2* vB = (float2*)S.m.bufB;          // v stage (36x36, stride 36)
        uint4*  dpB = (uint4*)S.m.bufB;          // diff stage (34x36, stride 36)

        if (tid < 256) S.m.sh[tid] = 0u;

        // y upsample table for this tile's 64 output rows
        if (tid < 64) {
            float pos = (float)(2 * tileY + tid) * SCALE;
            int i0 = clampi((int)floorf(pos), 0, HP - 2);
            S.m.ytab[tid] = make_float2(pos - (float)i0, __int_as_float(i0 - (tileY - 1)));
        }
        __syncthreads();   // sh zeroed before loader's hist atomics

        // pooled loader (from full-res), 4-halo, packed (F,M).
        // Histogram fused: for in-tile pixels, pF[0].x / pM[0].x ARE the
        // full-res even-coordinate samples the joint histogram needs.
        if (interior) {
            for (int s = tid; s < PR * PC; s += 512) {
                int sy = s / PC, sx = s % PC;
                int gy = gy0 + sy, gx = gx0 + sx;
                const float2* pF = (const float2*)(fF + (size_t)(2 * gy) * HF) + gx;
                float2 a = pF[0];
                float2 tF = f2add(a, pF[HF / 2]);
                const float2* pM = (const float2*)(fM + (size_t)(2 * gy) * HF) + gx;
                float2 m = pM[0];
                float2 tM = f2add(m, pM[HF / 2]);
                S.m.sFM[sy][sx] = make_float2(0.25f * (tF.x + tF.y), 0.25f * (tM.x + tM.y));
                if (sy >= 4 && sy < 36 && sx >= 4 && sx < 36)
                    hist_sample(S.m.sh, a.x, m.x);
            }
        } else {
            for (int s = tid; s < PR * PC; s += 512) {
                int sy = s / PC, sx = s % PC;
                int gy = clampi(gy0 + sy, 0, HP - 1), gx = clampi(gx0 + sx, 0, HP - 1);
                const float2* pF = (const float2*)(fF + (size_t)(2 * gy) * HF) + gx;
                float2 a = pF[0];
                float2 tF = f2add(a, pF[HF / 2]);
                const float2* pM = (const float2*)(fM + (size_t)(2 * gy) * HF) + gx;
                float2 m = pM[0];
                float2 tM = f2add(m, pM[HF / 2]);
                S.m.sFM[sy][sx] = make_float2(0.25f * (tF.x + tF.y), 0.25f * (tM.x + tM.y));
                if (sy >= 4 && sy < 36 && sx >= 4 && sx < 36)
                    hist_sample(S.m.sh, a.x, m.x);
            }
        }
        __syncthreads();

        if (interior) {
            // h -> A
            for (int s = tid; s < HROWS * 36; s += 512) {
                int u = s / 36, j = s % 36;
                A[s] = f2add(f2add(S.m.sFM[u][j], S.m.sFM[u][j + 1]), S.m.sFM[u][j + 2]);
            }
            __syncthreads();
            // variance_pre -> vB
            for (int s = tid; s < VROWS * 36; s += 512) {
                int iy = s / 36, jx = s % 36;
                float2 pm = f2add(f2add(A[s], A[s + 36]), A[s + 72]);
                float2 d = f2fma(pm, NNINTH, S.m.sFM[iy + 2][jx + 2]);
                vB[s] = f2mul(d, d);
            }
            __syncthreads();
            // hv -> A (h dead)
            for (int s = tid; s < VROWS * 34; s += 512) {
                int iy = s / 34, mc = s % 34;
                A[iy * 36 + mc] = f2add(f2add(vB[iy * 36 + mc], vB[iy * 36 + mc + 1]),
                                        vB[iy * 36 + mc + 2]);
            }
            __syncthreads();
        } else {
            // border: variance_pre (clamped taps) -> vB
            for (int s = tid; s < VROWS * 36; s += 512) {
                int iy = s / 36, jx = s % 36;
                int gv = tileY - 2 + iy, gc = tileX - 2 + jx;
                float2 pm = make_float2(0.f, 0.f);
                #pragma unroll
                for (int aa = 0; aa < 3; aa++) {
                    int rr = clampi(gv - 2 + aa, 0, HP - 1) - gy0;
                    #pragma unroll
                    for (int bb = 0; bb < 3; bb++) {
                        int cc = clampi(gc - 2 + bb, 0, HP - 1) - gx0;
                        pm = f2add(pm, S.m.sFM[rr][cc]);
                    }
                }
                float2 d = f2fma(pm, NNINTH, S.m.sFM[iy + 2][jx + 2]);
                vB[s] = f2mul(d, d);
            }
            __syncthreads();
            // border: -inv pre-stage -> A (so dp can overwrite vB); sign folded in
            for (int s = tid; s < DR * DC; s += 512) {
                int a = s / DC, b2 = s % DC;
                int gdy = tileY - 1 + a, gdx = tileX - 1 + b2;
                float2 vs = make_float2(0.f, 0.f);
                #pragma unroll
                for (int dy2 = -1; dy2 <= 1; dy2++) {
                    int iy = clampi(gdy + dy2, 0, HP - 1) - (tileY - 2);
                    #pragma unroll
                    for (int dx2 = -1; dx2 <= 1; dx2++) {
                        int jx = clampi(gdx + dx2, 0, HP - 1) - (tileX - 2);
                        vs = f2add(vs, vB[iy * 36 + jx]);
                    }
                }
                float varF = fmaxf(vs.x * (1.0f / 9.0f), 1e-4f);
                float varM = fmaxf(vs.y * (1.0f / 9.0f), 1e-4f);
                A[a * 36 + b2] = make_float2(-LOG2E / (varF * 2.0f + 1e-6f),
                                             -LOG2E / (varM * 2.0f + 1e-6f));
            }
            __syncthreads();
        }

        // diff channels on DRxDC; exponent via ex2 (-log2e folded into inv)
        {
            const int offdx[8] = {-2, -2, -2, 0, 0, 2, 2, 2};
            const int offdy[8] = {-2, 0, 2, -2, 2, -2, 0, 2};
            for (int s = tid; s < DR * DC; s += 512) {
                int a = s / DC, b2 = s % DC;
                float2 iFM;
                if (interior) {
                    float2 vs = f2add(f2add(A[a * 36 + b2], A[(a + 1) * 36 + b2]),
                                      A[(a + 2) * 36 + b2]);
                    float varF = fmaxf(vs.x * (1.0f / 9.0f), 1e-4f);
                    float varM = fmaxf(vs.y * (1.0f / 9.0f), 1e-4f);
                    iFM = make_float2(-LOG2E / (varF * 2.0f + 1e-6f),
                                      -LOG2E / (varM * 2.0f + 1e-6f));
                } else {
                    iFM = A[a * 36 + b2];
                }
                float2 c0 = S.m.sFM[a + 3][b2 + 3];

                float2 e2[8];
                float2 sum2 = make_float2(1e-8f, 1e-8f);
                if (interior) {
                    #pragma unroll
                    for (int c = 0; c < 8; c++) {
                        float2 o = S.m.sFM[a + 3 + offdy[c]][b2 + 3 + offdx[c]];
                        float2 df = make_float2(c0.x - o.x, c0.y - o.y);
                        float2 q = f2mul(f2mul(df, df), iFM);
                        e2[c] = make_float2(ex2f(q.x), ex2f(q.y));
                        sum2 = f2add(sum2, e2[c]);
                    }
                } else {
                    #pragma unroll
                    for (int c = 0; c < 8; c++) {
                        int rr = clampi(tileY - 1 + a + offdy[c], 0, HP - 1) - gy0;
                        int cc = clampi(tileX - 1 + b2 + offdx[c], 0, HP - 1) - gx0;
                        float2 o = S.m.sFM[rr][cc];
                        float2 df = make_float2(c0.x - o.x, c0.y - o.y);
                        float2 q = f2mul(f2mul(df, df), iFM);
                        e2[c] = make_float2(ex2f(q.x), ex2f(q.y));
                        sum2 = f2add(sum2, e2[c]);
                    }
                }
                float rF = 1.0f / sum2.x, rM = 1.0f / sum2.y;
                __half2 tmp4[4];
                #pragma unroll
                for (int p = 0; p < 4; p++) {
                    float d0 = e2[2 * p].x * rF - e2[2 * p].y * rM;
                    float d1 = e2[2 * p + 1].x * rF - e2[2 * p + 1].y * rM;
                    tmp4[p] = __floats2half2_rn(d0, d1);
                }
                dpB[a * 36 + b2] = *(uint4*)tmp4;
            }
        }
        __syncthreads();

        // ---- in-tile bilinear upsample (align corners) + |.| accumulate ----
        float acc = 0.f;
        {
            int lx = tid & 63;
            float posx = (float)(2 * tileX + lx) * SCALE;
            int j0 = clampi((int)floorf(posx), 0, HP - 2);
            float fx = posx - (float)j0;
            int rx = j0 - (tileX - 1);       // 0..32
            __half2 wx0 = __float2half2_rn(1.0f - fx), wx1 = __float2half2_rn(fx);

            #pragma unroll
            for (int half = 0; half < 2; half++) {
                int qy = (tid >> 6) + half * 8;    // 0..15
                float2 yt[4];
                #pragma unroll
                for (int k = 0; k < 4; k++) yt[k] = S.m.ytab[qy * 4 + k];
                int rbase = __float_as_int(yt[0].y);

                __half2 xv[4][4];
                #pragma unroll
                for (int rr = 0; rr < 4; rr++) {
                    int row = min(rbase + rr, DR - 1);
                    uint4 t0 = dpB[row * 36 + rx];
                    uint4 t1 = dpB[row * 36 + rx + 1];
                    const __half2* h0 = (const __half2*)&t0;
                    const __half2* h1 = (const __half2*)&t1;
                    #pragma unroll
                    for (int p = 0; p < 4; p++)
                        xv[p][rr] = __hfma2(h1[p], wx1, __hmul2(h0[p], wx0));
                }
                #pragma unroll
                for (int k = 0; k < 4; k++) {
                    float fy = yt[k].x;
                    int ri = __float_as_int(yt[k].y) - rbase;   // 0..2
                    __half2 wy0 = __float2half2_rn(1.0f - fy), wy1 = __float2half2_rn(fy);
                    #pragma unroll
                    for (int p = 0; p < 4; p++) {
                        __half2 val = __hfma2(xv[p][ri + 1], wy1, __hmul2(xv[p][ri], wy0));
                        float2 vf = __half22float2(val);
                        acc += fabsf(vf.x) + fabsf(vf.y);
                    }
                }
            }
        }
        // block reduce (deterministic)
        #pragma unroll
        for (int o = 16; o > 0; o >>= 1)
            acc += __shfl_down_sync(0xffffffffu, acc, o);
        if ((tid & 31) == 0) S.m.red[tid >> 5] = acc;
        __syncthreads();
        if (tid == 0) {
            float s = 0.f;
            #pragma unroll
            for (int k = 0; k < 16; k++) s += S.m.red[k];
            g_part_mind[blk] = s;
        }
        // flush per-tile histogram
        if (tid < 256) {
            unsigned int cnt = S.m.sh[tid];
            if (cnt) atomicAdd(&g_hist_agg[b][tid], cnt);
        }
    } else {
        // ================= regularizer strip =================
        int q = blk - 512;           // 0..255
        int b = q >> 5;
        int st = q & 31;             // 8 pooled rows per strip
        int sel = tid >> 8;          // 0 -> u, 1 -> v
        int tt = tid & 255;
        const float* base = flow + ((size_t)b * 2 + sel) * HF * HF;
        float (*sbuf)[256] = sel ? S.r.sv : S.r.su;

        #pragma unroll
        for (int rr = 0; rr < 10; rr++) {
            int py = clampi(st * 8 - 1 + rr, 0, HP - 1);
            const float2* p2 = (const float2*)(base + (size_t)(2 * py) * HF) + tt;
            float2 t2 = f2add(p2[0], p2[HF / 2]);
            sbuf[rr][tt] = 0.25f * (t2.x + t2.y);
        }
        __syncthreads();

        int x = tid & 255;
        int rg = tid >> 8;
        int xm = max(x - 1, 0), xp = min(x + 1, HP - 1);
        float acc = 0.f;
        #pragma unroll
        for (int k = 0; k < 4; k++) {
            int rr = rg * 4 + k + 1;
            float u00 = S.r.su[rr - 1][xm], u01 = S.r.su[rr - 1][x], u02 = S.r.su[rr - 1][xp];
            float u10 = S.r.su[rr][xm],     u11 = S.r.su[rr][x],     u12 = S.r.su[rr][xp];
            float u20 = S.r.su[rr + 1][xm], u21 = S.r.su[rr + 1][x], u22 = S.r.su[rr + 1][xp];
            float v00 = S.r.sv[rr - 1][xm], v01 = S.r.sv[rr - 1][x], v02 = S.r.sv[rr - 1][xp];
            float v10 = S.r.sv[rr][xm],     v11 = S.r.sv[rr][x],     v12 = S.r.sv[rr][xp];
            float v20 = S.r.sv[rr + 1][xm], v21 = S.r.sv[rr + 1][x], v22 = S.r.sv[rr + 1][xp];

            float gxu = (u02 + 2.f * u12 + u22) - (u00 + 2.f * u10 + u20);
            float gyu = (u20 + 2.f * u21 + u22) - (u00 + 2.f * u01 + u02);
            float lpu = u01 + u10 + u12 + u21 - 4.f * u11;
            float gxv = (v02 + 2.f * v12 + v22) - (v00 + 2.f * v10 + v20);
            float gyv = (v20 + 2.f * v21 + v22) - (v00 + 2.f * v01 + v02);
            float lpv = v01 + v10 + v12 + v21 - 4.f * v11;

            float gm = gxu * gxu + gyu * gyu + gxv * gxv + gyv * gyv;
            float lm = lpu * lpu + lpv * lpv;
            acc += fminf(gm, 100.0f) + fminf(lm, 100.0f);
        }
        __syncthreads();
        S.r.red[tid] = acc;
        __syncthreads();
        #pragma unroll
        for (int s = 256; s > 0; s >>= 1) {
            if (tid < s) S.r.red[tid] += S.r.red[tid + s];
            __syncthreads();
        }
        if (tid == 0) g_part_reg[q] = S.r.red[0];
    }

    // ================= last-block-done fused epilogue =================
    __threadfence();
    __syncthreads();
    __shared__ unsigned int isLast;
    if (tid == 0) isLast = (atomicAdd(&g_done, 1u) == (unsigned)(gridDim.x - 1)) ? 1u : 0u;
    __syncthreads();
    if (!isLast) return;

    int w = tid >> 5;
    int lane = tid & 31;

    if (w < 8) {
        int b = w;
        uint4 u0 = __ldcg((const uint4*)&g_hist_agg[b][0] + lane * 2);
        uint4 u1 = __ldcg((const uint4*)&g_hist_agg[b][0] + lane * 2 + 1);
        ((uint4*)&g_hist_agg[b][0])[lane * 2] = make_uint4(0, 0, 0, 0);
        ((uint4*)&g_hist_agg[b][0])[lane * 2 + 1] = make_uint4(0, 0, 0, 0);
        float p[8];
        p[0] = (float)u0.x * (1.0f / 65536.0f); p[1] = (float)u0.y * (1.0f / 65536.0f);
        p[2] = (float)u0.z * (1.0f / 65536.0f); p[3] = (float)u0.w * (1.0f / 65536.0f);
        p[4] = (float)u1.x * (1.0f / 65536.0f); p[5] = (float)u1.y * (1.0f / 65536.0f);
        p[6] = (float)u1.z * (1.0f / 65536.0f); p[7] = (float)u1.w * (1.0f / 65536.0f);
        #pragma unroll
        for (int k = 0; k < 8; k++) S.e.hp[b][lane * 8 + k] = p[k];
        __syncwarp();
        if (lane < 16) {
            float s = 0.f;
            #pragma unroll
            for (int j = 0; j < 16; j++) s += S.e.hp[b][lane * 16 + j];
            S.e.xh[b][lane] = s + 1e-5f;
        } else {
            int col = lane - 16;
            float s = 0.f;
            #pragma unroll
            for (int i = 0; i < 16; i++) s += S.e.hp[b][i * 16 + col];
            S.e.yh[b][col] = s + 1e-5f;
        }
        __syncwarp();
        int row = (lane * 8) >> 4;
        float xr = S.e.xh[b][row];
        int cbase = (lane * 8) & 15;
        float term = 0.f;
        #pragma unroll
        for (int k = 0; k < 8; k++) {
            float hpe = p[k] + 1e-5f;
            term += hpe * (__logf(hpe) - __logf(xr * S.e.yh[b][cbase + k]));
        }
        #pragma unroll
        for (int o = 16; o > 0; o >>= 1)
            term += __shfl_down_sync(0xffffffffu, term, o);
        if (lane == 0) {
            float mi = term;
            float hx = 0.f, hy = 0.f;
            #pragma unroll
            for (int k = 0; k < 16; k++) {
                hx -= S.e.xh[b][k] * __logf(S.e.xh[b][k]);
                hy -= S.e.yh[b][k] * __logf(S.e.yh[b][k]);
            }
            float se = hx + hy;
            float nmi = (se < 1e-10f) ? 0.0f : 2.0f * mi / se;
            S.e.nmi[b] = fminf(fmaxf(nmi, -1.0f), 1.0f);
        }
    } else if (w < 12) {
        // mind partials: 512 floats across warps 8-11 (float4/lane)
        int i = (w - 8) * 32 + lane;   // 0..127
        float4 v;
        v.x = __ldcg(&g_part_mind[4 * i]);
        v.y = __ldcg(&g_part_mind[4 * i + 1]);
        v.z = __ldcg(&g_part_mind[4 * i + 2]);
        v.w = __ldcg(&g_part_mind[4 * i + 3]);
        float s = (v.x + v.y) + (v.z + v.w);
        #pragma unroll
        for (int o = 16; o > 0; o >>= 1)
            s += __shfl_down_sync(0xffffffffu, s, o);
        if (lane == 0) S.e.mind_p[w - 8] = s;
    } else if (w < 14) {
        // reg partials: 256 floats across warps 12-13 (float4/lane)
        int j = (w - 12) * 32 + lane;   // 0..63
        float4 r4;
        r4.x = __ldcg(&g_part_reg[4 * j]);
        r4.y = __ldcg(&g_part_reg[4 * j + 1]);
        r4.z = __ldcg(&g_part_reg[4 * j + 2]);
        r4.w = __ldcg(&g_part_reg[4 * j + 3]);
        float sr = (r4.x + r4.y) + (r4.z + r4.w);
        #pragma unroll
        for (int o = 16; o > 0; o >>= 1)
            sr += __shfl_down_sync(0xffffffffu, sr, o);
        if (lane == 0) S.e.reg_p[w - 12] = sr;
    }
    __syncthreads();

    if (tid == 0) {
        float mind = S.e.mind_p[0] + S.e.mind_p[1] + S.e.mind_p[2] + S.e.mind_p[3];
        float reg = S.e.reg_p[0] + S.e.reg_p[1];
        float accn = 0.f;
        #pragma unroll
        for (int b = 0; b < BATCH; b++) accn += S.e.nmi[b];
        float mm = fminf(fmaxf(accn * (1.0f / BATCH), -1.0f), 1.0f);
        out[0] = -mm
               + 5.0f * (mind * (1.0f / 16777216.0f))
               + 0.1f * (reg * (1.0f / 524288.0f));
        g_done = 0u;   // reset for next graph replay
    }
}

// ---------------- launch ----------------
extern "C" void kernel_launch(void* const* d_in, const int* in_sizes, int n_in,
                              void* d_out, int out_size) {
    const float* fixed = (const float*)d_in[0];
    const float* moved = (const float*)d_in[1];
    const float* flow  = (const float*)d_in[2];
    if (n_in >= 3) {
        int fi = -1;
        for (int i = 0; i < 3; i++) if (in_sizes[i] == 2 * BATCH * HF * HF) fi = i;
        if (fi == 0) { flow = (const float*)d_in[0]; fixed = (const float*)d_in[1]; moved = (const float*)d_in[2]; }
        else if (fi == 1) { fixed = (const float*)d_in[0]; flow = (const float*)d_in[1]; moved = (const float*)d_in[2]; }
    }

    k_main<<<768, 512>>>(fixed, moved, flow, (float*)d_out);
}